// round 4
// baseline (speedup 1.0000x reference)
#include <cuda_runtime.h>
#include <math.h>

#define HH 96
#define WW 96
#define NSAMP 8

// scratch: per-sample max(distA, distB)
__device__ float g_pair[NSAMP];

__device__ __forceinline__ int getbit(unsigned w0, unsigned w1, unsigned w2, int x) {
    unsigned w = (x < 32) ? w0 : (x < 64) ? w1 : w2;
    return (w >> (x & 31)) & 1;
}

__global__ void __launch_bounds__(96) haus_main(const float* __restrict__ pred,
                                                const float* __restrict__ tgt) {
    const int n    = blockIdx.x;       // sample
    const int tx   = threadIdx.x;      // 0..95 (column / row worker)
    const int lane = tx & 31;
    const int warp = tx >> 5;

    __shared__ unsigned mA[HH][3];     // mask A bit-rows
    __shared__ unsigned mB[HH][3];     // mask B bit-rows
    __shared__ short    ndA[HH][WW];   // per-row nearest-set-bit dist in A
    __shared__ short    ndB[HH][WW];   // per-row nearest-set-bit dist in B
    __shared__ int      red[96];
    __shared__ float    s_dist[2];
    __shared__ int      s_anyA, s_anyB;

    const float* p = pred + n * (HH * WW);
    const float* t = tgt  + n * (HH * WW);

    // ---- build bitmasks: mask = round_half_even(v) > 0.5 ----
    for (int r = 0; r < HH; ++r) {
        bool ba = rintf(p[r * WW + tx]) > 0.5f;
        bool bb = rintf(t[r * WW + tx]) > 0.5f;
        unsigned wa = __ballot_sync(0xffffffffu, ba);
        unsigned wb = __ballot_sync(0xffffffffu, bb);
        if (lane == 0) { mA[r][warp] = wa; mB[r][warp] = wb; }
    }
    __syncthreads();

    // ---- per-row 1D nearest-set-bit distances (thread tx owns row tx) ----
    {
        const int r = tx;
        unsigned a0 = mA[r][0], a1 = mA[r][1], a2 = mA[r][2];
        unsigned b0 = mB[r][0], b1 = mB[r][1], b2 = mB[r][2];
        int lastA = -30000, lastB = -30000;
        for (int x = 0; x < WW; ++x) {
            if (getbit(a0, a1, a2, x)) lastA = x;
            if (getbit(b0, b1, b2, x)) lastB = x;
            ndA[r][x] = (short)min(10000, x - lastA);
            ndB[r][x] = (short)min(10000, x - lastB);
        }
        int nextA = 30000, nextB = 30000;
        for (int x = WW - 1; x >= 0; --x) {
            if (getbit(a0, a1, a2, x)) nextA = x;
            if (getbit(b0, b1, b2, x)) nextB = x;
            int da = min((int)ndA[r][x], min(10000, nextA - x));
            int db = min((int)ndB[r][x], min(10000, nextB - x));
            ndA[r][x] = (short)da;
            ndB[r][x] = (short)db;
        }
    }

    // ---- any-point flags for A and B ----
    if (tx == 0) {
        int anyA = 0, anyB = 0;
        for (int r = 0; r < HH; ++r) {
            anyA |= (mA[r][0] | mA[r][1] | mA[r][2]) != 0;
            anyB |= (mB[r][0] | mB[r][1] | mB[r][2]) != 0;
        }
        s_anyA = anyA;
        s_anyB = anyB;
    }
    __syncthreads();

    const int wi = tx >> 5, bi = tx & 31;

    // dir 0: src = A & ~B, tgt = B (use ndB).  dir 1: src = B & ~A, tgt = A (use ndA).
    for (int dir = 0; dir < 2; ++dir) {
        const short (*nd)[WW] = dir ? ndA : ndB;
        int colmax = -1;  // max over src points in this column of min-sq-dist

        for (int sy = 0; sy < HH; ++sy) {
            unsigned sa = mA[sy][wi], sb = mB[sy][wi];
            unsigned s  = dir ? (sb & ~sa) : (sa & ~sb);
            if ((s >> bi) & 1) {
                int best = 1 << 30;
                // outward row search with early break: off^2 >= best => done
                for (int off = 0; off < HH; ++off) {
                    int dy2 = off * off;
                    if (dy2 >= best) break;
                    int r0 = sy - off;
                    if (r0 >= 0) {
                        int v = nd[r0][tx];
                        best = min(best, dy2 + v * v);
                    }
                    int r1 = sy + off;
                    if (off && r1 < HH) {
                        int v = nd[r1][tx];
                        best = min(best, dy2 + v * v);
                    }
                }
                colmax = max(colmax, best);
            }
        }

        red[tx] = colmax;
        __syncthreads();
        if (tx == 0) {
            int gmax = -1;
            for (int i = 0; i < 96; ++i) gmax = max(gmax, red[i]);
            int anyTgt = dir ? s_anyA : s_anyB;
            float dist;
            if (gmax < 0)        dist = 0.0f;         // empty source set
            else if (!anyTgt)    dist = 1e9f;         // empty target set
            else                 dist = sqrtf((float)gmax) * (1.0f / 96.0f);
            s_dist[dir] = dist;
        }
        __syncthreads();
    }

    if (tx == 0) g_pair[n] = fmaxf(s_dist[0], s_dist[1]);
}

__global__ void haus_final(float* __restrict__ out) {
    if (threadIdx.x == 0) {
        float s = 0.0f;
        for (int i = 0; i < NSAMP; ++i) s += g_pair[i];
        out[0] = s * (1.0f / NSAMP);
    }
}

extern "C" void kernel_launch(void* const* d_in, const int* in_sizes, int n_in,
                              void* d_out, int out_size) {
    const float* pred = (const float*)d_in[0];
    const float* tgt  = (const float*)d_in[1];
    float* out = (float*)d_out;
    haus_main<<<NSAMP, 96>>>(pred, tgt);
    haus_final<<<1, 32>>>(out);
}

// round 6
// speedup vs baseline: 4.6792x; 4.6792x over previous
#include <cuda_runtime.h>
#include <math.h>

#define HH 96
#define WW 96
#define NSAMP 8
#define NT 768            // threads per block
#define NBLK 64           // 8 samples * 2 dirs * 4 column-quarters
#define LD_PER 12         // 9216 / 768

// cross-block scratch
__device__ float g_part[NBLK];
__device__ int   g_count;

// nearest set-bit distance in a 96-bit row mask (w0,w1,w2) from position x,
// clamped to 10000. Branch-free word selection + clz/ffs.
__device__ __forceinline__ int nearestDist(unsigned w0, unsigned w1, unsigned w2, int x) {
    int k = x >> 5, b = x & 31;
    unsigned lm = (2u << b) - 1u;   // bits 0..b   (b=31 -> all ones)
    unsigned hm = ~0u << b;         // bits b..31
    // highest set bit at position <= x
    unsigned c0 = (k == 0) ? (w0 & lm) : w0;
    unsigned c1 = (k == 0) ? 0u : ((k == 1) ? (w1 & lm) : w1);
    unsigned c2 = (k == 2) ? (w2 & lm) : 0u;
    int h = c2 ? (95 - __clz(c2))
          : (c1 ? (63 - __clz(c1))
          : (c0 ? (31 - __clz(c0)) : -20000));
    // lowest set bit at position >= x
    unsigned d0 = (k == 0) ? (w0 & hm) : 0u;
    unsigned d1 = (k == 0) ? w1 : ((k == 1) ? (w1 & hm) : 0u);
    unsigned d2 = (k == 2) ? (w2 & hm) : w2;        // FIXED (was inverted)
    int l = d0 ? (__ffs(d0) - 1)
          : (d1 ? (31 + __ffs(d1))
          : (d2 ? (63 + __ffs(d2)) : 20000));
    return min(min(x - h, l - x), 10000);
}

__global__ void __launch_bounds__(NT, 1)
haus_fused(const float* __restrict__ pred, const float* __restrict__ tgt,
           float* __restrict__ out) {
    const int b   = blockIdx.x;
    const int n   = b >> 3;          // sample
    const int dir = (b >> 2) & 1;    // 0: src=A\B tgt=B ; 1: src=B\A tgt=A
    const int qx  = b & 3;           // column quarter
    const int tid = threadIdx.x;

    __shared__ unsigned mA[HH][3];
    __shared__ unsigned mB[HH][3];
    __shared__ short    nd[HH][WW];  // per-row nearest-target-bit distance
    __shared__ int      s_gmax, s_anyT, s_last;

    if (tid == 0) { s_gmax = -1; s_anyT = 0; s_last = 0; }
    __syncthreads();

    const float* p = pred + n * (HH * WW);
    const float* t = tgt  + n * (HH * WW);

    // ---- prefetch ALL global data first (MLP=24), then ballot into bitmasks ----
    float pv[LD_PER], tv[LD_PER];
#pragma unroll
    for (int k = 0; k < LD_PER; ++k) {
        pv[k] = p[tid + NT * k];
        tv[k] = t[tid + NT * k];
    }
#pragma unroll
    for (int k = 0; k < LD_PER; ++k) {
        int i = tid + NT * k;
        unsigned wa = __ballot_sync(0xffffffffu, rintf(pv[k]) > 0.5f);
        unsigned wb = __ballot_sync(0xffffffffu, rintf(tv[k]) > 0.5f);
        if ((tid & 31) == 0) {
            int r = i / WW, ws = (i % WW) >> 5;
            mA[r][ws] = wa; mB[r][ws] = wb;
            if (dir ? wa : wb) s_anyT = 1;   // target non-empty flag
        }
    }
    __syncthreads();

    // ---- nd table: fully parallel, 12 points per thread, branch-free ----
#pragma unroll
    for (int k = 0; k < LD_PER; ++k) {
        int i = tid + NT * k;
        int r = i / WW, xx = i % WW;
        unsigned w0, w1, w2;
        if (dir) { w0 = mA[r][0]; w1 = mA[r][1]; w2 = mA[r][2]; }
        else     { w0 = mB[r][0]; w1 = mB[r][1]; w2 = mB[r][2]; }
        nd[r][xx] = (short)nearestDist(w0, w1, w2, xx);
    }
    __syncthreads();

    // ---- directed Hausdorff: thread handles (column x, 3 rows) ----
    const int x  = qx * 24 + (tid % 24);   // 24 columns per block
    const int g  = tid / 24;               // 0..31 row groups
    const int wi = x >> 5, bi = x & 31;

    int colmax = -1;
#pragma unroll
    for (int k = 0; k < 3; ++k) {
        int sy = g * 3 + k;
        unsigned sa = mA[sy][wi], sb = mB[sy][wi];
        unsigned s  = dir ? (sb & ~sa) : (sa & ~sb);
        if ((s >> bi) & 1) {
            int best = 1 << 30;
            for (int off = 0; off < HH; ++off) {
                int dy2 = off * off;
                if (dy2 >= best) break;
                int r0 = sy - off;
                if (r0 >= 0) { int v = nd[r0][x]; best = min(best, dy2 + v * v); }
                int r1 = sy + off;
                if (off && r1 < HH) { int v = nd[r1][x]; best = min(best, dy2 + v * v); }
            }
            colmax = max(colmax, best);
        }
    }

    int wmax = __reduce_max_sync(0xffffffffu, colmax);
    if ((tid & 31) == 0) atomicMax(&s_gmax, wmax);
    __syncthreads();

    if (tid == 0) {
        int gmax = s_gmax;
        float dist = (gmax < 0) ? 0.0f
                   : (!s_anyT  ? 1e9f
                   : sqrtf((float)gmax) * (1.0f / 96.0f));
        g_part[b] = dist;
        __threadfence();
        int old = atomicAdd(&g_count, 1);
        s_last = (old == NBLK - 1);
    }
    __syncthreads();

    // ---- last block reduces mean(haus) over samples and resets counter ----
    if (s_last) {
        __threadfence();
        if (tid < NSAMP) {
            float d0 = -1.0f, d1 = -1.0f;
#pragma unroll
            for (int q = 0; q < 4; ++q) {
                d0 = fmaxf(d0, g_part[tid * 8 + q]);       // dir 0 quarters
                d1 = fmaxf(d1, g_part[tid * 8 + 4 + q]);   // dir 1 quarters
            }
            float h = fmaxf(d0, d1);
#pragma unroll
            for (int off = 4; off; off >>= 1)
                h += __shfl_down_sync(0x000000ffu, h, off);
            if (tid == 0) { out[0] = h * 0.125f; g_count = 0; }
        }
    }
}

extern "C" void kernel_launch(void* const* d_in, const int* in_sizes, int n_in,
                              void* d_out, int out_size) {
    const float* pred = (const float*)d_in[0];
    const float* tgt  = (const float*)d_in[1];
    haus_fused<<<NBLK, NT>>>(pred, tgt, (float*)d_out);
}

// round 7
// speedup vs baseline: 4.7995x; 1.0257x over previous
#include <cuda_runtime.h>
#include <math.h>

#define HH 96
#define WW 96
#define NSAMP 8
#define NT 768            // threads per block (load phase)
#define LD_PER 12         // 9216 / 768
#define TLIM 128          // dilation covers d^2 <= 128; beyond -> fallback
#define BIGFLAG 0x3f000000

// cross-block scratch
__device__ float g_part[NSAMP];
__device__ int   g_count;

// nearest set-bit distance in a 96-bit row mask from position x (clamped 10000)
__device__ __forceinline__ int nearestDist(unsigned w0, unsigned w1, unsigned w2, int x) {
    int k = x >> 5, b = x & 31;
    unsigned lm = (2u << b) - 1u;
    unsigned hm = ~0u << b;
    unsigned c0 = (k == 0) ? (w0 & lm) : w0;
    unsigned c1 = (k == 0) ? 0u : ((k == 1) ? (w1 & lm) : w1);
    unsigned c2 = (k == 2) ? (w2 & lm) : 0u;
    int h = c2 ? (95 - __clz(c2))
          : (c1 ? (63 - __clz(c1))
          : (c0 ? (31 - __clz(c0)) : -20000));
    unsigned d0 = (k == 0) ? (w0 & hm) : 0u;
    unsigned d1 = (k == 0) ? w1 : ((k == 1) ? (w1 & hm) : 0u);
    unsigned d2 = (k == 2) ? (w2 & hm) : w2;
    int l = d0 ? (__ffs(d0) - 1)
          : (d1 ? (31 + __ffs(d1))
          : (d2 ? (63 + __ffs(d2)) : 20000));
    return min(min(x - h, l - x), 10000);
}

// OR into (c0,c1,c2) the 96-bit target row shifted by +dx and -dx
__device__ __forceinline__ void accum(unsigned& c0, unsigned& c1, unsigned& c2,
                                      const unsigned* t, int dx) {
    unsigned t0 = t[0], t1 = t[1], t2 = t[2];
    if (dx == 0) { c0 |= t0; c1 |= t1; c2 |= t2; return; }
    int q = dx >> 5, b = dx & 31;
    unsigned i0, i1, i2;
    // shift left (toward higher x)
    if (q == 0)      { i0 = t0; i1 = t1; i2 = t2; }
    else if (q == 1) { i0 = 0;  i1 = t0; i2 = t1; }
    else             { i0 = 0;  i1 = 0;  i2 = t0; }
    c0 |= i0 << b;
    c1 |= __funnelshift_l(i0, i1, b);
    c2 |= __funnelshift_l(i1, i2, b);
    // shift right (toward lower x)
    if (q == 0)      { i0 = t0; i1 = t1; i2 = t2; }
    else if (q == 1) { i0 = t1; i1 = t2; i2 = 0;  }
    else             { i0 = t2; i1 = 0;  i2 = 0;  }
    c2 |= i2 >> b;
    c1 |= __funnelshift_r(i1, i2, b);
    c0 |= __funnelshift_r(i0, i1, b);
}

__global__ void __launch_bounds__(NT, 1)
haus_fused(const float* __restrict__ pred, const float* __restrict__ tgt,
           float* __restrict__ out) {
    const int n   = blockIdx.x;     // sample
    const int tid = threadIdx.x;

    __shared__ unsigned mA[HH][3];
    __shared__ unsigned mB[HH][3];
    __shared__ int s_wmax[6];
    __shared__ int s_anyA, s_anyB, s_last;

    const float* p = pred + n * (HH * WW);
    const float* t = tgt  + n * (HH * WW);

    // ---- prefetch all global data (MLP=24) ----
    float pv[LD_PER], tv[LD_PER];
#pragma unroll
    for (int k = 0; k < LD_PER; ++k) {
        pv[k] = p[tid + NT * k];
        tv[k] = t[tid + NT * k];
    }
    if (tid == 0) { s_anyA = 0; s_anyB = 0; }
    __syncthreads();

    // ---- ballot into bitmasks ----
#pragma unroll
    for (int k = 0; k < LD_PER; ++k) {
        int i = tid + NT * k;
        unsigned wa = __ballot_sync(0xffffffffu, rintf(pv[k]) > 0.5f);
        unsigned wb = __ballot_sync(0xffffffffu, rintf(tv[k]) > 0.5f);
        if ((tid & 31) == 0) {
            int r = i / WW, ws = (i % WW) >> 5;
            mA[r][ws] = wa; mB[r][ws] = wb;
            if (wa) s_anyA = 1;
            if (wb) s_anyB = 1;
        }
    }
    __syncthreads();

    // ---- per-row dilation: warps 0-2 = dir 0 (src=A\B, tgt=B); warps 3-5 = dir 1 ----
    if (tid < 192) {
        const int dir = tid >= 96;
        const int r   = tid - dir * 96;
        const unsigned (*S)[3]  = dir ? mB : mA;   // src mask
        const unsigned (*Tg)[3] = dir ? mA : mB;   // tgt mask
        unsigned r0 = S[r][0] & ~Tg[r][0];
        unsigned r1 = S[r][1] & ~Tg[r][1];
        unsigned r2 = S[r][2] & ~Tg[r][2];
        const int anyT = dir ? s_anyA : s_anyB;

        int ans;
        if (!(r0 | r1 | r2)) {
            ans = -1;                    // no source points in this row
        } else if (!anyT) {
            ans = BIGFLAG;               // source exists, target empty -> 1e9
        } else {
            ans = 0;
            for (int T = 1; T <= TLIM; ++T) {
                for (int dy = 0; dy * dy <= T; ++dy) {
                    int dx2 = T - dy * dy;
                    int dx = (int)(sqrtf((float)dx2) + 0.5f);
                    if (dx * dx != dx2) continue;
                    unsigned c0 = 0, c1 = 0, c2 = 0;
                    int ra = r - dy;
                    if (ra >= 0) accum(c0, c1, c2, Tg[ra], dx);
                    int rb = r + dy;
                    if (dy && rb < HH) accum(c0, c1, c2, Tg[rb], dx);
                    r0 &= ~c0; r1 &= ~c1; r2 &= ~c2;
                    if (!(r0 | r1 | r2)) { ans = T; goto rowdone; }
                }
            }
            // fallback: rare far points (exact), d^2 > TLIM dominates earlier ones
            for (int wb = 0; wb < 3; ++wb) {
                unsigned w = (wb == 0) ? r0 : ((wb == 1) ? r1 : r2);
                while (w) {
                    int x = wb * 32 + (__ffs(w) - 1);
                    w &= w - 1;
                    int best = 1 << 30;
                    for (int off = 0; off < HH; ++off) {
                        int dy2 = off * off;
                        if (dy2 >= best) break;
                        int ra = r - off;
                        if (ra >= 0) {
                            int v = nearestDist(Tg[ra][0], Tg[ra][1], Tg[ra][2], x);
                            best = min(best, dy2 + v * v);
                        }
                        int rb = r + off;
                        if (off && rb < HH) {
                            int v = nearestDist(Tg[rb][0], Tg[rb][1], Tg[rb][2], x);
                            best = min(best, dy2 + v * v);
                        }
                    }
                    ans = max(ans, best);
                }
            }
            rowdone: ;
        }

        int wmax = __reduce_max_sync(0xffffffffu, ans);
        if ((tid & 31) == 0) s_wmax[tid >> 5] = wmax;
    }
    __syncthreads();

    if (tid == 0) {
        int m0 = max(s_wmax[0], max(s_wmax[1], s_wmax[2]));
        int m1 = max(s_wmax[3], max(s_wmax[4], s_wmax[5]));
        float d0 = (m0 < 0) ? 0.0f : ((m0 >= BIGFLAG) ? 1e9f : sqrtf((float)m0) * (1.0f / 96.0f));
        float d1 = (m1 < 0) ? 0.0f : ((m1 >= BIGFLAG) ? 1e9f : sqrtf((float)m1) * (1.0f / 96.0f));
        g_part[n] = fmaxf(d0, d1);
        __threadfence();
        int old = atomicAdd(&g_count, 1);
        s_last = (old == NSAMP - 1);
    }
    __syncthreads();

    // ---- last block computes the mean over samples and resets the counter ----
    if (s_last) {
        __threadfence();
        if (tid < NSAMP) {
            float h = g_part[tid];
#pragma unroll
            for (int off = 4; off; off >>= 1)
                h += __shfl_down_sync(0x000000ffu, h, off);
            if (tid == 0) { out[0] = h * (1.0f / NSAMP); g_count = 0; }
        }
    }
}

extern "C" void kernel_launch(void* const* d_in, const int* in_sizes, int n_in,
                              void* d_out, int out_size) {
    const float* pred = (const float*)d_in[0];
    const float* tgt  = (const float*)d_in[1];
    haus_fused<<<NSAMP, NT>>>(pred, tgt, (float*)d_out);
}

// round 8
// speedup vs baseline: 6.8640x; 1.4301x over previous
#include <cuda_runtime.h>
#include <math.h>

#define HH 96
#define WW 96
#define NSAMP 8
#define NT 768            // threads per block (load phase)
#define LD_PER 12         // 9216 / 768
#define EMPTY_T2 100000000  // sentinel: d^2 >= this means "target set empty"

// cross-block scratch
__device__ float g_part[NSAMP];
__device__ int   g_count;

// nearest set-bit distance in a 96-bit row mask from position x (clamped 10000)
__device__ __forceinline__ int nearestDist(unsigned w0, unsigned w1, unsigned w2, int x) {
    int k = x >> 5, b = x & 31;
    unsigned lm = (2u << b) - 1u;
    unsigned hm = ~0u << b;
    unsigned c0 = (k == 0) ? (w0 & lm) : w0;
    unsigned c1 = (k == 0) ? 0u : ((k == 1) ? (w1 & lm) : w1);
    unsigned c2 = (k == 2) ? (w2 & lm) : 0u;
    int h = c2 ? (95 - __clz(c2))
          : (c1 ? (63 - __clz(c1))
          : (c0 ? (31 - __clz(c0)) : -20000));
    unsigned d0 = (k == 0) ? (w0 & hm) : 0u;
    unsigned d1 = (k == 0) ? w1 : ((k == 1) ? (w1 & hm) : 0u);
    unsigned d2 = (k == 2) ? (w2 & hm) : w2;
    int l = d0 ? (__ffs(d0) - 1)
          : (d1 ? (31 + __ffs(d1))
          : (d2 ? (63 + __ffs(d2)) : 20000));
    return min(min(x - h, l - x), 10000);
}

// OR into (c0,c1,c2) the 96-bit target row shifted by +dx and -dx (dx <= 31)
__device__ __forceinline__ void accum(unsigned& c0, unsigned& c1, unsigned& c2,
                                      const unsigned* t, int dx) {
    unsigned t0 = t[0], t1 = t[1], t2 = t[2];
    if (dx == 0) { c0 |= t0; c1 |= t1; c2 |= t2; return; }
    c0 |= t0 << dx;
    c1 |= __funnelshift_l(t0, t1, dx);
    c2 |= __funnelshift_l(t1, t2, dx);
    c2 |= t2 >> dx;
    c1 |= __funnelshift_r(t1, t2, dx);
    c0 |= __funnelshift_r(t0, t1, dx);
}

__global__ void __launch_bounds__(NT, 1)
haus_fused(const float* __restrict__ pred, const float* __restrict__ tgt,
           float* __restrict__ out) {
    const int n   = blockIdx.x;     // sample
    const int tid = threadIdx.x;

    __shared__ unsigned mA[HH][3];
    __shared__ unsigned mB[HH][3];
    __shared__ int s_wmax[6];
    __shared__ int s_last;

    const float* p = pred + n * (HH * WW);
    const float* t = tgt  + n * (HH * WW);

    // ---- prefetch all global data (MLP=24) ----
    float pv[LD_PER], tv[LD_PER];
#pragma unroll
    for (int k = 0; k < LD_PER; ++k) {
        pv[k] = p[tid + NT * k];
        tv[k] = t[tid + NT * k];
    }
    // ---- ballot into bitmasks ----
#pragma unroll
    for (int k = 0; k < LD_PER; ++k) {
        int i = tid + NT * k;
        unsigned wa = __ballot_sync(0xffffffffu, rintf(pv[k]) > 0.5f);
        unsigned wb = __ballot_sync(0xffffffffu, rintf(tv[k]) > 0.5f);
        if ((tid & 31) == 0) {
            int r = i / WW, ws = (i % WW) >> 5;
            mA[r][ws] = wa; mB[r][ws] = wb;
        }
    }
    __syncthreads();

    // ---- per-row dilation: warps 0-2 = dir 0 (src=A\B, tgt=B); warps 3-5 = dir 1 ----
    if (tid < 192) {
        const int dir = tid >= 96;
        const int r   = tid - dir * 96;
        const unsigned (*S)[3]  = dir ? mB : mA;   // src mask
        const unsigned (*Tg)[3] = dir ? mA : mB;   // tgt mask
        unsigned r0 = S[r][0] & ~Tg[r][0];
        unsigned r1 = S[r][1] & ~Tg[r][1];
        unsigned r2 = S[r][2] & ~Tg[r][2];

        int ans;
        if (!(r0 | r1 | r2)) {
            ans = -1;                    // no source points in this row
        } else {
            ans = 0;
            // compile-time offset table: all (dy,dx) with T=dy^2+dx^2 <= 32,
            // ascending T, 'last' marks end of each equal-T group.
            static const signed char EDY[30]  = {0,1, 1, 0,2, 1,2, 2, 0,3, 1,3, 2,3, 0,4, 1,4, 3, 2,4, 0,5,3,4, 1,5, 2,5, 4};
            static const signed char EDX[30]  = {1,0, 1, 2,0, 2,1, 2, 3,0, 3,1, 3,2, 4,0, 4,1, 3, 4,2, 5,0,4,3, 5,1, 5,2, 4};
            static const signed char ET [30]  = {1,1, 2, 4,4, 5,5, 8, 9,9, 10,10, 13,13, 16,16, 17,17, 18, 20,20, 25,25,25,25, 26,26, 29,29, 32};
            static const signed char ELAST[30]= {0,1, 1, 0,1, 0,1, 1, 0,1, 0,1,  0,1,  0,1,  0,1,  1,  0,1,  0,0,0,1,  0,1,  0,1,  1};
#pragma unroll
            for (int e = 0; e < 30; ++e) {
                const int dy = EDY[e], dx = EDX[e];
                unsigned c0 = 0, c1 = 0, c2 = 0;
                int ra = r - dy;
                if (ra >= 0) accum(c0, c1, c2, Tg[ra], dx);
                if (dy) {
                    int rb = r + dy;
                    if (rb < HH) accum(c0, c1, c2, Tg[rb], dx);
                }
                r0 &= ~c0; r1 &= ~c1; r2 &= ~c2;
                if (ELAST[e] && !(r0 | r1 | r2)) { ans = ET[e]; goto rowdone; }
            }
            // fallback: surviving points have d^2 > 32 (exact search; also
            // handles the empty-target case via the 10000 sentinel -> 1e8)
            for (int wb = 0; wb < 3; ++wb) {
                unsigned w = (wb == 0) ? r0 : ((wb == 1) ? r1 : r2);
                while (w) {
                    int x = wb * 32 + (__ffs(w) - 1);
                    w &= w - 1;
                    int best = 1 << 30;
                    for (int off = 0; off < HH; ++off) {
                        int dy2 = off * off;
                        if (dy2 >= best) break;
                        int ra = r - off;
                        if (ra >= 0) {
                            int v = nearestDist(Tg[ra][0], Tg[ra][1], Tg[ra][2], x);
                            best = min(best, dy2 + v * v);
                        }
                        int rb = r + off;
                        if (off && rb < HH) {
                            int v = nearestDist(Tg[rb][0], Tg[rb][1], Tg[rb][2], x);
                            best = min(best, dy2 + v * v);
                        }
                    }
                    ans = max(ans, best);
                }
            }
            rowdone: ;
        }

        int wmax = __reduce_max_sync(0xffffffffu, ans);
        if ((tid & 31) == 0) s_wmax[tid >> 5] = wmax;
    }
    __syncthreads();

    if (tid == 0) {
        int m0 = max(s_wmax[0], max(s_wmax[1], s_wmax[2]));
        int m1 = max(s_wmax[3], max(s_wmax[4], s_wmax[5]));
        float d0 = (m0 < 0) ? 0.0f : ((m0 >= EMPTY_T2) ? 1e9f : sqrtf((float)m0) * (1.0f / 96.0f));
        float d1 = (m1 < 0) ? 0.0f : ((m1 >= EMPTY_T2) ? 1e9f : sqrtf((float)m1) * (1.0f / 96.0f));
        g_part[n] = fmaxf(d0, d1);
        // acq_rel atomic: release publishes g_part[n]; acquire (in the winner)
        // synchronizes with all other blocks' releases. No membar needed.
        int old;
        asm volatile("atom.acq_rel.gpu.global.add.s32 %0, [%1], %2;"
                     : "=r"(old) : "l"(&g_count), "r"(1) : "memory");
        s_last = (old == NSAMP - 1);
    }
    __syncthreads();   // propagates tid0's acquire to the whole block

    // ---- last block computes the mean over samples and resets the counter ----
    if (s_last) {
        if (tid < NSAMP) {
            float h = g_part[tid];
#pragma unroll
            for (int off = 4; off; off >>= 1)
                h += __shfl_down_sync(0x000000ffu, h, off);
            if (tid == 0) { out[0] = h * (1.0f / NSAMP); g_count = 0; }
        }
    }
}

extern "C" void kernel_launch(void* const* d_in, const int* in_sizes, int n_in,
                              void* d_out, int out_size) {
    const float* pred = (const float*)d_in[0];
    const float* tgt  = (const float*)d_in[1];
    haus_fused<<<NSAMP, NT>>>(pred, tgt, (float*)d_out);
}

// round 10
// speedup vs baseline: 7.0453x; 1.0264x over previous
#include <cuda_runtime.h>
#include <math.h>

#define HH 96
#define WW 96
#define NSAMP 8
#define NT 768            // threads per block (load phase)
#define LD_PER 12         // 9216 / 768
#define EMPTY_T2 100000000  // sentinel: d^2 >= this means "target set empty"

// cross-block scratch
__device__ float g_part[NSAMP];
__device__ int   g_count;

// nearest set-bit distance in a 96-bit row mask from position x (clamped 10000)
__device__ __forceinline__ int nearestDist(unsigned w0, unsigned w1, unsigned w2, int x) {
    int k = x >> 5, b = x & 31;
    unsigned lm = (2u << b) - 1u;
    unsigned hm = ~0u << b;
    unsigned c0 = (k == 0) ? (w0 & lm) : w0;
    unsigned c1 = (k == 0) ? 0u : ((k == 1) ? (w1 & lm) : w1);
    unsigned c2 = (k == 2) ? (w2 & lm) : 0u;
    int h = c2 ? (95 - __clz(c2))
          : (c1 ? (63 - __clz(c1))
          : (c0 ? (31 - __clz(c0)) : -20000));
    unsigned d0 = (k == 0) ? (w0 & hm) : 0u;
    unsigned d1 = (k == 0) ? w1 : ((k == 1) ? (w1 & hm) : 0u);
    unsigned d2 = (k == 2) ? (w2 & hm) : w2;
    int l = d0 ? (__ffs(d0) - 1)
          : (d1 ? (31 + __ffs(d1))
          : (d2 ? (63 + __ffs(d2)) : 20000));
    return min(min(x - h, l - x), 10000);
}

// OR into (c0,c1,c2) the 96-bit target row shifted by +dx and -dx (dx <= 31)
__device__ __forceinline__ void accum(unsigned& c0, unsigned& c1, unsigned& c2,
                                      const unsigned* t, int dx) {
    unsigned t0 = t[0], t1 = t[1], t2 = t[2];
    if (dx == 0) { c0 |= t0; c1 |= t1; c2 |= t2; return; }
    c0 |= t0 << dx;
    c1 |= __funnelshift_l(t0, t1, dx);
    c2 |= __funnelshift_l(t1, t2, dx);
    c2 |= t2 >> dx;
    c1 |= __funnelshift_r(t1, t2, dx);
    c0 |= __funnelshift_r(t0, t1, dx);
}

__global__ void __launch_bounds__(NT, 1)
haus_fused(const float* __restrict__ pred, const float* __restrict__ tgt,
           float* __restrict__ out) {
    const int n   = blockIdx.x;     // sample
    const int tid = threadIdx.x;

    __shared__ unsigned mA[HH][3];
    __shared__ unsigned mB[HH][3];
    __shared__ int s_wmax[6];

    const float* p = pred + n * (HH * WW);
    const float* t = tgt  + n * (HH * WW);

    // ---- prefetch all global data (MLP=24) ----
    float pv[LD_PER], tv[LD_PER];
#pragma unroll
    for (int k = 0; k < LD_PER; ++k) {
        pv[k] = p[tid + NT * k];
        tv[k] = t[tid + NT * k];
    }
    // ---- ballot into bitmasks (round_half_even(v) > 0.5  <=>  v > 0.5) ----
#pragma unroll
    for (int k = 0; k < LD_PER; ++k) {
        int i = tid + NT * k;
        unsigned wa = __ballot_sync(0xffffffffu, pv[k] > 0.5f);
        unsigned wb = __ballot_sync(0xffffffffu, tv[k] > 0.5f);
        if ((tid & 31) == 0) {
            int r = i / WW, ws = (i % WW) >> 5;
            mA[r][ws] = wa; mB[r][ws] = wb;
        }
    }
    __syncthreads();

    // ---- per-row dilation: warps 0-2 = dir 0 (src=A\B, tgt=B); warps 3-5 = dir 1 ----
    if (tid < 192) {
        const int dir = tid >= 96;
        const int r   = tid - dir * 96;
        const unsigned (*S)[3]  = dir ? mB : mA;   // src mask
        const unsigned (*Tg)[3] = dir ? mA : mB;   // tgt mask
        unsigned r0 = S[r][0] & ~Tg[r][0];
        unsigned r1 = S[r][1] & ~Tg[r][1];
        unsigned r2 = S[r][2] & ~Tg[r][2];

        int ans;
        if (!(r0 | r1 | r2)) {
            ans = -1;                    // no source points in this row
        } else {
            ans = 0;
            // compile-time offset table: all (dy,dx) with T=dy^2+dx^2 <= 32,
            // ascending T, 'last' marks end of each equal-T group.
            static const signed char EDY[30]  = {0,1, 1, 0,2, 1,2, 2, 0,3, 1,3, 2,3, 0,4, 1,4, 3, 2,4, 0,5,3,4, 1,5, 2,5, 4};
            static const signed char EDX[30]  = {1,0, 1, 2,0, 2,1, 2, 3,0, 3,1, 3,2, 4,0, 4,1, 3, 4,2, 5,0,4,3, 5,1, 5,2, 4};
            static const signed char ET [30]  = {1,1, 2, 4,4, 5,5, 8, 9,9, 10,10, 13,13, 16,16, 17,17, 18, 20,20, 25,25,25,25, 26,26, 29,29, 32};
            static const signed char ELAST[30]= {0,1, 1, 0,1, 0,1, 1, 0,1, 0,1,  0,1,  0,1,  0,1,  1,  0,1,  0,0,0,1,  0,1,  0,1,  1};
#pragma unroll
            for (int e = 0; e < 30; ++e) {
                const int dy = EDY[e], dx = EDX[e];
                unsigned c0 = 0, c1 = 0, c2 = 0;
                int ra = r - dy;
                if (ra >= 0) accum(c0, c1, c2, Tg[ra], dx);
                if (dy) {
                    int rb = r + dy;
                    if (rb < HH) accum(c0, c1, c2, Tg[rb], dx);
                }
                r0 &= ~c0; r1 &= ~c1; r2 &= ~c2;
                if (ELAST[e] && !(r0 | r1 | r2)) { ans = ET[e]; goto rowdone; }
            }
            // fallback: surviving points have d^2 > 32 (exact search; also
            // handles the empty-target case via the 10000 sentinel -> 1e8)
            for (int wb = 0; wb < 3; ++wb) {
                unsigned w = (wb == 0) ? r0 : ((wb == 1) ? r1 : r2);
                while (w) {
                    int x = wb * 32 + (__ffs(w) - 1);
                    w &= w - 1;
                    int best = 1 << 30;
                    for (int off = 0; off < HH; ++off) {
                        int dy2 = off * off;
                        if (dy2 >= best) break;
                        int ra = r - off;
                        if (ra >= 0) {
                            int v = nearestDist(Tg[ra][0], Tg[ra][1], Tg[ra][2], x);
                            best = min(best, dy2 + v * v);
                        }
                        int rb = r + off;
                        if (off && rb < HH) {
                            int v = nearestDist(Tg[rb][0], Tg[rb][1], Tg[rb][2], x);
                            best = min(best, dy2 + v * v);
                        }
                    }
                    ans = max(ans, best);
                }
            }
            rowdone: ;
        }

        int wmax = __reduce_max_sync(0xffffffffu, ans);
        if ((tid & 31) == 0) s_wmax[tid >> 5] = wmax;
    }
    __syncthreads();

    // ---- tail: tid0 only; no further block-wide sync needed ----
    if (tid == 0) {
        int m0 = max(s_wmax[0], max(s_wmax[1], s_wmax[2]));
        int m1 = max(s_wmax[3], max(s_wmax[4], s_wmax[5]));
        float d0 = (m0 < 0) ? 0.0f : ((m0 >= EMPTY_T2) ? 1e9f : sqrtf((float)m0) * (1.0f / 96.0f));
        float d1 = (m1 < 0) ? 0.0f : ((m1 >= EMPTY_T2) ? 1e9f : sqrtf((float)m1) * (1.0f / 96.0f));
        g_part[n] = fmaxf(d0, d1);
        // acq_rel atomic: release publishes g_part[n]; acquire in the winner
        // synchronizes with all other blocks' releases.
        int old;
        asm volatile("atom.acq_rel.gpu.global.add.s32 %0, [%1], %2;"
                     : "=r"(old) : "l"(&g_count), "r"(1) : "memory");
        if (old == NSAMP - 1) {
            // winner: 8 independent L2 loads (one round-trip), fixed-order sum
            float s = 0.0f;
#pragma unroll
            for (int i = 0; i < NSAMP; ++i) s += __ldcg(&g_part[i]);
            out[0] = s * (1.0f / NSAMP);
            g_count = 0;   // reset for next graph replay (stream-ordered)
        }
    }
}

extern "C" void kernel_launch(void* const* d_in, const int* in_sizes, int n_in,
                              void* d_out, int out_size) {
    const float* pred = (const float*)d_in[0];
    const float* tgt  = (const float*)d_in[1];
    haus_fused<<<NSAMP, NT>>>(pred, tgt, (float*)d_out);
}